// round 16
// baseline (speedup 1.0000x reference)
#include <cuda_runtime.h>
#include <cstdint>

#define N        1024
#define NN       (1<<20)
#define NZ       24
#define PAIRS    12
#define ROI2     512
#define LO       256
#define EXT      64
#define INNER    896
#define SNRV     200.0f
#define BKG      110.0f
#define ITN      2
#define KSEL0    524287u
#define KSEL1    524288u

#define ROWS     4
#define TPB      128
#define WREG     2184        /* floats per warp region; %32==8 -> conflict-free block staging */
#define APL      3           /* planes per accumulate block */

// ---------------- static device scratch ----------------
__device__ float2   g_W [(size_t)PAIRS * NN];
__device__ float2   g_W2[(size_t)PAIRS * NN];
__device__ float2   g_KhT[NN];           // TRANSPOSED: g_KhT[kx*N+ky] = Kh(ky,kx)
__device__ float    g_ImgExp[NN];
__device__ float    g_ImgEst[NN];
__device__ float2   g_tw[32];            // W_1024^lane
__device__ float    g_partial[256];
__device__ float    g_scale;             // 1/(N^2*Ksum)
__device__ unsigned g_hist[3*65536];
__device__ unsigned g_sel[4];
__device__ float    g_medScale;

__device__ __constant__ float TWC[16] = {
    1.0f, 0.980785280403230f, 0.923879532511287f, 0.831469612302545f,
    0.707106781186548f, 0.555570233019602f, 0.382683432365090f, 0.195090322016128f,
    0.0f, -0.195090322016128f, -0.382683432365090f, -0.555570233019602f,
    -0.707106781186548f, -0.831469612302545f, -0.923879532511287f, -0.980785280403230f};
__device__ __constant__ float TWS[16] = {
    0.0f, 0.195090322016128f, 0.382683432365090f, 0.555570233019602f,
    0.707106781186548f, 0.831469612302545f, 0.923879532511287f, 0.980785280403230f,
    1.0f, 0.980785280403230f, 0.923879532511287f, 0.831469612302545f,
    0.707106781186548f, 0.555570233019602f, 0.382683432365090f, 0.195090322016128f};

__device__ __forceinline__ float2 cmul(float2 a, float2 b){
    return make_float2(a.x*b.x - a.y*b.y, a.x*b.y + a.y*b.x);
}

// fully-unrolled 32-point FFT in registers, natural in -> natural out
template<int INV>
__device__ __forceinline__ void fft32(float2 r[32]){
    #define SW(a,b) { float2 t_ = r[a]; r[a] = r[b]; r[b] = t_; }
    SW(1,16) SW(2,8) SW(3,24) SW(5,20) SW(6,12) SW(7,28)
    SW(9,18) SW(11,26) SW(13,22) SW(15,30) SW(19,25) SW(23,29)
    #undef SW
    #pragma unroll
    for (int s = 1; s <= 5; s++){
        const int m = 1 << s, h = m >> 1;
        #pragma unroll
        for (int k = 0; k < 32; k += m){
            #pragma unroll
            for (int j = 0; j < h; j++){
                const int ti = j << (5 - s);
                float2 b = r[k+j+h], t;
                if (ti == 0)       t = b;
                else if (ti == 8)  t = INV ? make_float2(-b.y, b.x) : make_float2(b.y, -b.x);
                else {
                    float2 w = make_float2(TWC[ti], INV ? TWS[ti] : -TWS[ti]);
                    t = cmul(b, w);
                }
                float2 a = r[k+j];
                r[k+j]   = make_float2(a.x + t.x, a.y + t.y);
                r[k+j+h] = make_float2(a.x - t.x, a.y - t.y);
            }
        }
    }
}

// twiddle r[k] *= W^(lane*k), FOUR interleaved chains (serial depth ~7 cmuls)
__device__ __forceinline__ void twiddle_apply(float2 r[32], float2 w1){
    float2 w2 = cmul(w1, w1);
    float2 w3 = cmul(w2, w1);
    float2 w4 = cmul(w2, w2);
    float2 c1 = w1, c2 = w2, c3 = w3, c0 = w4;
    r[1] = cmul(r[1], c1);
    r[2] = cmul(r[2], c2);
    r[3] = cmul(r[3], c3);
    #pragma unroll
    for (int k = 4; k < 32; k += 4){
        r[k]   = cmul(r[k],   c0);
        c1 = cmul(c1, w4);  r[k+1] = cmul(r[k+1], c1);
        c2 = cmul(c2, w4);  r[k+2] = cmul(r[k+2], c2);
        c3 = cmul(c3, w4);  r[k+3] = cmul(r[k+3], c3);
        c0 = cmul(c0, w4);
    }
}

// four-step 1024-pt FFT core. In: r[j] = x[lane + 32*j]. Out: r[k1] = X[32*k1 + lane].
// 32x32 transpose via XOR-swizzled float2 smem: conflict-free both directions.
template<int INV>
__device__ __forceinline__ void core(float2 r[32], float2* T2, int lane){
    fft32<INV>(r);
    float2 w1 = g_tw[lane];
    if (INV) w1.y = -w1.y;
    twiddle_apply(r, w1);
    __syncwarp();
    #pragma unroll
    for (int k = 0; k < 32; k++) T2[32*k + (lane ^ k)] = r[k];
    __syncwarp();
    #pragma unroll
    for (int n = 0; n < 32; n++) r[n] = T2[32*lane + (n ^ lane)];
    fft32<INV>(r);
}

// SoA output staging: warp-local Tx[i]=X[i].x, Ty[i]=X[i].y for i=0..1023
__device__ __forceinline__ void stage_out(const float2 r[32], float* Tx, float* Ty, int lane){
    __syncwarp();
    #pragma unroll
    for (int k = 0; k < 32; k++){ Tx[32*k + lane] = r[k].x; Ty[32*k + lane] = r[k].y; }
}

// ---------------- setup ----------------
__global__ void k_ksum(const float4* __restrict__ cr){
    __shared__ float s[256];
    if (blockIdx.x == 0 && threadIdx.x < 32){
        double a = -6.283185307179586 * (double)threadIdx.x / (double)N;
        g_tw[threadIdx.x] = make_float2((float)cos(a), (float)sin(a));
    }
    float acc = 0.f;
    for (int i = blockIdx.x*blockDim.x + threadIdx.x; i < NN/4; i += gridDim.x*blockDim.x){
        float4 v = cr[i];
        acc += (v.x + v.y) + (v.z + v.w);
    }
    s[threadIdx.x] = acc; __syncthreads();
    for (int o = 128; o > 0; o >>= 1){
        if (threadIdx.x < o) s[threadIdx.x] += s[threadIdx.x+o];
        __syncthreads();
    }
    if (threadIdx.x == 0) g_partial[blockIdx.x] = s[0];
}

__global__ void k_kh(const float* __restrict__ cr, const float* __restrict__ ci){
    if (blockIdx.x == 0 && threadIdx.x == 0){
        double s = 0.0;
        for (int i = 0; i < 256; i++) s += (double)g_partial[i];
        g_scale = (float)(1.0 / (1048576.0 * s));
    }
    int i = blockIdx.x*blockDim.x + threadIdx.x;
    if (i >= NN) return;
    int y = i >> 10, x = i & (N-1);
    int ny = (N - y) & (N-1), nx = (N - x) & (N-1);
    float kr = cr[i], ki = ci[i];
    float mr = cr[ny*N + nx], mi = ci[ny*N + nx];
    g_KhT[(size_t)x*N + y] = make_float2(0.5f*(kr + mr), 0.5f*(ki - mi));
}

__global__ void k_imgexp(const float* __restrict__ img){
    int i = blockIdx.x*blockDim.x + threadIdx.x;
    if (i >= NN) return;
    int y = i >> 10, x = i & (N-1);
    float v = 0.f;
    if (y >= EXT && y < N-EXT && x >= EXT && x < N-EXT){
        float t = img[(y-EXT)*INNER + (x-EXT)] - BKG;
        v = t > 0.f ? t : 0.f;
    }
    g_ImgExp[i] = v;
}

// ---------------- stage 1: row FFT + transposed store ----------------
// MODE 0 blocks with p==0 also zero ImgEst (replaces a memset launch).
template<int MODE>   // 0: pack obj z-pairs (rows LO..HI), 1: Ratio image
__global__ void __launch_bounds__(TPB, 4)
k_fwd1(const float* __restrict__ obj, float2* __restrict__ dst){
    __shared__ float sh[ROWS*WREG];
    int tid = threadIdx.x, w = tid >> 5, lane = tid & 31;
    int p = blockIdx.y;
    int row0 = (MODE == 0 ? LO : 0) + blockIdx.x*ROWS;
    int row = row0 + w;
    float *Tx = sh + w*WREG, *Ty = Tx + 1088;
    float2 r[32];

    if (MODE == 0 && p == 0){
        // zero ImgEst stripe: 128 x-blocks x 2048 float4 = NN floats
        float4 z4 = make_float4(0.f, 0.f, 0.f, 0.f);
        float4* ez = ((float4*)g_ImgEst) + (size_t)blockIdx.x * 2048;
        #pragma unroll
        for (int t = 0; t < 2048/TPB; t++) ez[tid + t*TPB] = z4;
    }

    if (MODE == 0){
        const float* o0 = obj + (size_t)(2*p)*ROI2*ROI2 + (size_t)(row-LO)*ROI2 - LO;
        const float* o1 = o0 + (size_t)ROI2*ROI2;
        #pragma unroll
        for (int j = 0; j < 32; j++){
            int x = lane + 32*j;
            r[j] = (j >= 8 && j < 24) ? make_float2(o0[x], o1[x]) : make_float2(0.f, 0.f);
        }
    } else {
        float med = g_medScale;
        bool rowin = (row >= EXT && row < N-EXT);
        #pragma unroll
        for (int j = 0; j < 32; j++){
            int x = lane + 32*j;
            float v = 1.f;
            if (rowin && j >= 2 && j < 30)
                v = g_ImgExp[(size_t)row*N + x] / (g_ImgEst[(size_t)row*N + x] + med);
            r[j] = make_float2(v, 0.f);
        }
    }

    core<0>(r, (float2*)Tx, lane);
    stage_out(r, Tx, Ty, lane);
    __syncthreads();

    size_t poff = (size_t)p * NN;
    for (int e = tid; e < ROWS*N; e += TPB){
        int rr = e & 3, i = e >> 2;
        const float* B = sh + rr*WREG;
        __stcs(&dst[poff + (size_t)i*N + (row0 + rr)], make_float2(B[i], B[1088 + i]));
    }
}

// ---- stage 2 (fused): col FFT -> *KhT*scale -> inverse col FFT + transposed store ----
template<int GUARDED, int CONJ, int HALF>
__global__ void __launch_bounds__(TPB, 4)
k_mid(const float2* __restrict__ src, float2* __restrict__ dst){
    __shared__ float sh[ROWS*WREG];
    int tid = threadIdx.x, w = tid >> 5, lane = tid & 31;
    int p = blockIdx.y;
    int row0 = blockIdx.x*ROWS;
    int row = row0 + w;
    size_t poff = (size_t)p * NN;
    const float2* s = src + poff + (size_t)row*N;
    float *Tx = sh + w*WREG, *Ty = Tx + 1088;
    float2 r[32];

    // prefetch this row's Kh (8KB) into L2 so the mid-kernel spectral load hits
    {
        const char* kp = (const char*)(g_KhT + (size_t)row*N);
        asm volatile("prefetch.global.L2 [%0];" :: "l"(kp + lane*256));
        asm volatile("prefetch.global.L2 [%0];" :: "l"(kp + lane*256 + 128));
    }

    #pragma unroll
    for (int j = 0; j < 32; j++)
        r[j] = (!GUARDED || (j >= 8 && j < 24)) ? __ldcs(&s[lane + 32*j]) : make_float2(0.f, 0.f);

    core<0>(r, (float2*)Tx, lane);

    const float2* kh = g_KhT + (size_t)row*N;
    float sc = g_scale;
    #pragma unroll 8
    for (int k = 0; k < 32; k++){
        float2 kv = kh[32*k + lane];
        if (CONJ) kv.y = -kv.y;
        float2 a = r[k];
        r[k] = make_float2((a.x*kv.x - a.y*kv.y)*sc, (a.x*kv.y + a.y*kv.x)*sc);
    }

    core<1>(r, (float2*)Tx, lane);
    stage_out(r, Tx, Ty, lane);
    __syncthreads();

    if (!HALF){
        for (int e = tid; e < ROWS*N; e += TPB){
            int rr = e & 3, i = e >> 2;
            const float* B = sh + rr*WREG;
            __stcs(&dst[poff + (size_t)i*N + (row0 + rr)], make_float2(B[i], B[1088 + i]));
        }
    } else {
        for (int e = tid; e < ROWS*ROI2; e += TPB){
            int rr = e & 3, i = LO + (e >> 2);
            const float* B = sh + rr*WREG;
            __stcs(&dst[poff + (size_t)i*N + (row0 + rr)], make_float2(B[i], B[1088 + i]));
        }
    }
}

// ---- stage 3a: inverse row FFT over APL planes, register-accumulate ----
__global__ void __launch_bounds__(TPB, 4)
k_last_accum(const float2* __restrict__ src){
    __shared__ float sh[ROWS*WREG];
    int tid = threadIdx.x, w = tid >> 5, lane = tid & 31;
    int row = blockIdx.x*ROWS + w;
    int p0 = blockIdx.y*APL;
    float* Tx = sh + w*WREG;
    float acc[32];
    #pragma unroll
    for (int k = 0; k < 32; k++) acc[k] = 0.f;

    for (int p = p0; p < p0 + APL; p++){
        const float2* s = src + (size_t)p*NN + (size_t)row*N;
        float2 r[32];
        #pragma unroll
        for (int j = 0; j < 32; j++) r[j] = __ldcs(&s[lane + 32*j]);
        core<1>(r, (float2*)Tx, lane);
        #pragma unroll
        for (int k = 0; k < 32; k++)
            acc[k] += fmaxf(r[k].x, 0.f) + fmaxf(r[k].y, 0.f);
    }
    float* est = g_ImgEst + (size_t)row*N + lane;
    #pragma unroll
    for (int k = 0; k < 32; k++) atomicAdd(est + 32*k, acc[k]);
}

// ---------------- stage 3b: inverse row FFT + fused obj update ----------------
__global__ void __launch_bounds__(TPB, 4)
k_last_update(const float2* __restrict__ src, float* __restrict__ obj){
    __shared__ float sh[ROWS*WREG];
    int tid = threadIdx.x, w = tid >> 5, lane = tid & 31;
    int row = LO + blockIdx.x*ROWS + w;
    const float2* s = src + (size_t)row*N;
    float* Tx = sh + w*WREG;
    float2 r[32];
    #pragma unroll
    for (int j = 0; j < 32; j++) r[j] = __ldcs(&s[lane + 32*j]);
    core<1>(r, (float2*)Tx, lane);

    float b[16];
    #pragma unroll
    for (int k = 0; k < 16; k++) b[k] = fmaxf(r[k+8].x, 0.f);

    float* o = obj + (size_t)(row - LO)*ROI2 + lane;
    #pragma unroll
    for (int z = 0; z < NZ; z++){
        float* oz = o + (size_t)z*ROI2*ROI2;
        #pragma unroll
        for (int k = 0; k < 16; k++){
            int c = 32*(k+8) - LO;
            oz[c] *= b[k];
        }
    }
}

// ---------------- median (exact, 2-level radix select) ----------------
__global__ void k_hist_top(){
    for (int i = blockIdx.x*blockDim.x + threadIdx.x; i < NN; i += gridDim.x*blockDim.x){
        unsigned u = __float_as_uint(g_ImgEst[i]);
        atomicAdd(&g_hist[u >> 16], 1u);
    }
}

__global__ void k_scan_top(){
    __shared__ unsigned part[1024];
    int t = threadIdx.x;
    unsigned local = 0;
    for (int i = 0; i < 64; i++) local += g_hist[(t<<6) + i];
    part[t] = local; __syncthreads();
    for (int off = 1; off < 1024; off <<= 1){
        unsigned v = (t >= off) ? part[t-off] : 0u;
        __syncthreads();
        part[t] += v;
        __syncthreads();
    }
    unsigned cum = part[t] - local;
    for (int i = 0; i < 64; i++){
        unsigned c = g_hist[(t<<6) + i];
        if (KSEL0 >= cum && KSEL0 < cum + c){ g_sel[0] = (t<<6)+i; g_sel[1] = KSEL0 - cum; }
        if (KSEL1 >= cum && KSEL1 < cum + c){ g_sel[2] = (t<<6)+i; g_sel[3] = KSEL1 - cum; }
        cum += c;
    }
}

__global__ void k_hist_low(){
    unsigned b0 = g_sel[0], b1 = g_sel[2];
    for (int i = blockIdx.x*blockDim.x + threadIdx.x; i < NN; i += gridDim.x*blockDim.x){
        unsigned u = __float_as_uint(g_ImgEst[i]);
        unsigned hi = u >> 16, lo = u & 0xFFFFu;
        if (hi == b0) atomicAdd(&g_hist[65536  + lo], 1u);
        if (hi == b1) atomicAdd(&g_hist[131072 + lo], 1u);
    }
}

// also re-zeroes the whole hist array at the end (for the next iteration)
__global__ void k_scan_low(){
    __shared__ unsigned part[1024];
    __shared__ unsigned sval[2];
    int t = threadIdx.x;
    #pragma unroll
    for (int which = 0; which < 2; which++){
        const unsigned* H = g_hist + 65536*(which+1);
        unsigned local = 0;
        for (int i = 0; i < 64; i++) local += H[(t<<6) + i];
        part[t] = local; __syncthreads();
        for (int off = 1; off < 1024; off <<= 1){
            unsigned v = (t >= off) ? part[t-off] : 0u;
            __syncthreads();
            part[t] += v;
            __syncthreads();
        }
        unsigned cum = part[t] - local;
        unsigned k   = g_sel[which*2 + 1];
        unsigned bin = g_sel[which*2];
        for (int i = 0; i < 64; i++){
            unsigned c = H[(t<<6) + i];
            if (k >= cum && k < cum + c) sval[which] = (bin << 16) | ((t<<6) + i);
            cum += c;
        }
        __syncthreads();
    }
    if (t == 0){
        float v0 = __uint_as_float(sval[0]);
        float v1 = __uint_as_float(sval[1]);
        g_medScale = 0.5f*(v0 + v1) / SNRV;
    }
    // zero all 3 hist sections for the next iteration
    uint4 z = make_uint4(0u,0u,0u,0u);
    uint4* hz = (uint4*)g_hist;
    for (int i = t; i < (3*65536)/4; i += 1024) hz[i] = z;
}

// ---------------- launch sequence ----------------
extern "C" void kernel_launch(void* const* d_in, const int* in_sizes, int n_in,
                              void* d_out, int out_size)
{
    const float* imstack   = (const float*)d_in[0];
    const float* init_vol  = (const float*)d_in[1];
    const float* conv_real = (const float*)d_in[2];
    const float* conv_imag = (const float*)d_in[3];
    float* obj = (float*)d_out;

    void *wp, *w2p, *histPtr;
    cudaGetSymbolAddress(&wp,  g_W);
    cudaGetSymbolAddress(&w2p, g_W2);
    cudaGetSymbolAddress(&histPtr, g_hist);
    float2* W  = (float2*)wp;
    float2* W2 = (float2*)w2p;

    cudaMemcpyAsync(obj, init_vol, (size_t)NZ*ROI2*ROI2*sizeof(float),
                    cudaMemcpyDeviceToDevice, 0);

    dim3 gHalf12(ROI2/ROWS, PAIRS), g12(N/ROWS, PAIRS);
    dim3 gHalf1 (ROI2/ROWS, 1),     g1 (N/ROWS, 1);
    dim3 gAcc   (N/ROWS, PAIRS/APL);

    // prefix ordering: 5th launch (incl. memcpy) = k_mid -> ncu capture target
    k_ksum<<<256,256>>>((const float4*)conv_real);
    k_kh<<<NN/256,256>>>(conv_real, conv_imag);
    k_fwd1<0><<<gHalf12, TPB>>>(obj, W2);
    k_mid<1,0,0><<<g12, TPB>>>(W2, W);                  // <- ncu target
    k_imgexp<<<NN/256,256>>>(imstack);
    cudaMemsetAsync(histPtr, 0, 3*65536*sizeof(unsigned), 0);   // once; scan_low re-zeroes

    for (int it = 0; it < ITN; it++){
        if (it > 0){
            k_fwd1<0><<<gHalf12, TPB>>>(obj, W2);       // also zeroes ImgEst (p==0 blocks)
            k_mid<1,0,0><<<g12, TPB>>>(W2, W);
        }
        k_last_accum<<<gAcc, TPB>>>(W);

        // ---- exact median of ImgEst ----
        k_hist_top<<<512,256>>>();
        k_scan_top<<<1,1024>>>();
        k_hist_low<<<512,256>>>();
        k_scan_low<<<1,1024>>>();

        // ---- back projection: 3 fused stages ----
        k_fwd1<1><<<g1, TPB>>>(nullptr, W2);
        k_mid<0,1,1><<<g1, TPB>>>(W2, W);
        k_last_update<<<gHalf1, TPB>>>(W, obj);
    }
}

// round 17
// speedup vs baseline: 1.0081x; 1.0081x over previous
#include <cuda_runtime.h>
#include <cstdint>

#define N        1024
#define NN       (1<<20)
#define NZ       24
#define PAIRS    12
#define ROI2     512
#define LO       256
#define EXT      64
#define INNER    896
#define SNRV     200.0f
#define BKG      110.0f
#define ITN      2
#define KSEL0    524287u
#define KSEL1    524288u

#define ROWS     4
#define TPB      128
#define WREG     2184        /* floats per warp region; %32==8 -> conflict-free block staging */
#define APL      3           /* planes per accumulate block */

// ---------------- static device scratch ----------------
__device__ float2   g_W [(size_t)PAIRS * NN];
__device__ float2   g_W2[(size_t)PAIRS * NN];
__device__ float2   g_KhT[NN];           // TRANSPOSED: g_KhT[kx*N+ky] = Kh(ky,kx)
__device__ float    g_ImgExp[NN];
__device__ float    g_ImgEst[NN];
__device__ float2   g_tw[32];            // W_1024^lane
__device__ float    g_partial[256];
__device__ float    g_scale;             // 1/(N^2*Ksum)
__device__ unsigned g_hist[3*65536];
__device__ unsigned g_sel[4];
__device__ float    g_medScale;

__device__ __constant__ float TWC[16] = {
    1.0f, 0.980785280403230f, 0.923879532511287f, 0.831469612302545f,
    0.707106781186548f, 0.555570233019602f, 0.382683432365090f, 0.195090322016128f,
    0.0f, -0.195090322016128f, -0.382683432365090f, -0.555570233019602f,
    -0.707106781186548f, -0.831469612302545f, -0.923879532511287f, -0.980785280403230f};
__device__ __constant__ float TWS[16] = {
    0.0f, 0.195090322016128f, 0.382683432365090f, 0.555570233019602f,
    0.707106781186548f, 0.831469612302545f, 0.923879532511287f, 0.980785280403230f,
    1.0f, 0.980785280403230f, 0.923879532511287f, 0.831469612302545f,
    0.707106781186548f, 0.555570233019602f, 0.382683432365090f, 0.195090322016128f};

__device__ __forceinline__ float2 cmul(float2 a, float2 b){
    return make_float2(a.x*b.x - a.y*b.y, a.x*b.y + a.y*b.x);
}

// fully-unrolled 32-point FFT in registers, natural in -> natural out
template<int INV>
__device__ __forceinline__ void fft32(float2 r[32]){
    #define SW(a,b) { float2 t_ = r[a]; r[a] = r[b]; r[b] = t_; }
    SW(1,16) SW(2,8) SW(3,24) SW(5,20) SW(6,12) SW(7,28)
    SW(9,18) SW(11,26) SW(13,22) SW(15,30) SW(19,25) SW(23,29)
    #undef SW
    #pragma unroll
    for (int s = 1; s <= 5; s++){
        const int m = 1 << s, h = m >> 1;
        #pragma unroll
        for (int k = 0; k < 32; k += m){
            #pragma unroll
            for (int j = 0; j < h; j++){
                const int ti = j << (5 - s);
                float2 b = r[k+j+h], t;
                if (ti == 0)       t = b;
                else if (ti == 8)  t = INV ? make_float2(-b.y, b.x) : make_float2(b.y, -b.x);
                else {
                    float2 w = make_float2(TWC[ti], INV ? TWS[ti] : -TWS[ti]);
                    t = cmul(b, w);
                }
                float2 a = r[k+j];
                r[k+j]   = make_float2(a.x + t.x, a.y + t.y);
                r[k+j+h] = make_float2(a.x - t.x, a.y - t.y);
            }
        }
    }
}

// twiddle r[k] *= W^(lane*k), FOUR interleaved chains (serial depth ~7 cmuls)
__device__ __forceinline__ void twiddle_apply(float2 r[32], float2 w1){
    float2 w2 = cmul(w1, w1);
    float2 w3 = cmul(w2, w1);
    float2 w4 = cmul(w2, w2);
    float2 c1 = w1, c2 = w2, c3 = w3, c0 = w4;
    r[1] = cmul(r[1], c1);
    r[2] = cmul(r[2], c2);
    r[3] = cmul(r[3], c3);
    #pragma unroll
    for (int k = 4; k < 32; k += 4){
        r[k]   = cmul(r[k],   c0);
        c1 = cmul(c1, w4);  r[k+1] = cmul(r[k+1], c1);
        c2 = cmul(c2, w4);  r[k+2] = cmul(r[k+2], c2);
        c3 = cmul(c3, w4);  r[k+3] = cmul(r[k+3], c3);
        c0 = cmul(c0, w4);
    }
}

// four-step 1024-pt FFT core. In: r[j] = x[lane + 32*j]. Out: r[k1] = X[32*k1 + lane].
// 32x32 transpose via XOR-swizzled float2 smem: conflict-free both directions.
template<int INV>
__device__ __forceinline__ void core(float2 r[32], float2* T2, int lane){
    fft32<INV>(r);
    float2 w1 = g_tw[lane];
    if (INV) w1.y = -w1.y;
    twiddle_apply(r, w1);
    __syncwarp();
    #pragma unroll
    for (int k = 0; k < 32; k++) T2[32*k + (lane ^ k)] = r[k];
    __syncwarp();
    #pragma unroll
    for (int n = 0; n < 32; n++) r[n] = T2[32*lane + (n ^ lane)];
    fft32<INV>(r);
}

// SoA output staging: warp-local Tx[i]=X[i].x, Ty[i]=X[i].y for i=0..1023
__device__ __forceinline__ void stage_out(const float2 r[32], float* Tx, float* Ty, int lane){
    __syncwarp();
    #pragma unroll
    for (int k = 0; k < 32; k++){ Tx[32*k + lane] = r[k].x; Ty[32*k + lane] = r[k].y; }
}

// ---------------- setup ----------------
__global__ void k_ksum(const float4* __restrict__ cr){
    __shared__ float s[256];
    if (blockIdx.x == 0 && threadIdx.x < 32){
        double a = -6.283185307179586 * (double)threadIdx.x / (double)N;
        g_tw[threadIdx.x] = make_float2((float)cos(a), (float)sin(a));
    }
    float acc = 0.f;
    for (int i = blockIdx.x*blockDim.x + threadIdx.x; i < NN/4; i += gridDim.x*blockDim.x){
        float4 v = cr[i];
        acc += (v.x + v.y) + (v.z + v.w);
    }
    s[threadIdx.x] = acc; __syncthreads();
    for (int o = 128; o > 0; o >>= 1){
        if (threadIdx.x < o) s[threadIdx.x] += s[threadIdx.x+o];
        __syncthreads();
    }
    if (threadIdx.x == 0) g_partial[blockIdx.x] = s[0];
}

__global__ void k_kh(const float* __restrict__ cr, const float* __restrict__ ci){
    if (blockIdx.x == 0 && threadIdx.x == 0){
        double s = 0.0;
        for (int i = 0; i < 256; i++) s += (double)g_partial[i];
        g_scale = (float)(1.0 / (1048576.0 * s));
    }
    int i = blockIdx.x*blockDim.x + threadIdx.x;
    if (i >= NN) return;
    int y = i >> 10, x = i & (N-1);
    int ny = (N - y) & (N-1), nx = (N - x) & (N-1);
    float kr = cr[i], ki = ci[i];
    float mr = cr[ny*N + nx], mi = ci[ny*N + nx];
    g_KhT[(size_t)x*N + y] = make_float2(0.5f*(kr + mr), 0.5f*(ki - mi));
}

__global__ void k_imgexp(const float* __restrict__ img){
    int i = blockIdx.x*blockDim.x + threadIdx.x;
    if (i >= NN) return;
    int y = i >> 10, x = i & (N-1);
    float v = 0.f;
    if (y >= EXT && y < N-EXT && x >= EXT && x < N-EXT){
        float t = img[(y-EXT)*INNER + (x-EXT)] - BKG;
        v = t > 0.f ? t : 0.f;
    }
    g_ImgExp[i] = v;
}

// ---------------- stage 1: row FFT + transposed store ----------------
template<int MODE>   // 0: pack obj z-pairs (rows LO..HI), 1: Ratio image
__global__ void __launch_bounds__(TPB, 4)
k_fwd1(const float* __restrict__ obj, float2* __restrict__ dst){
    __shared__ float sh[ROWS*WREG];
    int tid = threadIdx.x, w = tid >> 5, lane = tid & 31;
    int p = blockIdx.y;
    int row0 = (MODE == 0 ? LO : 0) + blockIdx.x*ROWS;
    int row = row0 + w;
    float *Tx = sh + w*WREG, *Ty = Tx + 1088;
    float2 r[32];

    if (MODE == 0){
        const float* o0 = obj + (size_t)(2*p)*ROI2*ROI2 + (size_t)(row-LO)*ROI2 - LO;
        const float* o1 = o0 + (size_t)ROI2*ROI2;
        #pragma unroll
        for (int j = 0; j < 32; j++){
            int x = lane + 32*j;
            r[j] = (j >= 8 && j < 24) ? make_float2(o0[x], o1[x]) : make_float2(0.f, 0.f);
        }
    } else {
        float med = g_medScale;
        bool rowin = (row >= EXT && row < N-EXT);
        #pragma unroll
        for (int j = 0; j < 32; j++){
            int x = lane + 32*j;
            float v = 1.f;
            if (rowin && j >= 2 && j < 30)
                v = g_ImgExp[(size_t)row*N + x] / (g_ImgEst[(size_t)row*N + x] + med);
            r[j] = make_float2(v, 0.f);
        }
    }

    core<0>(r, (float2*)Tx, lane);
    stage_out(r, Tx, Ty, lane);
    __syncthreads();

    size_t poff = (size_t)p * NN;
    for (int e = tid; e < ROWS*N; e += TPB){
        int rr = e & 3, i = e >> 2;
        const float* B = sh + rr*WREG;
        __stcs(&dst[poff + (size_t)i*N + (row0 + rr)], make_float2(B[i], B[1088 + i]));
    }
}

// ---- stage 2 (fused): col FFT -> *KhT*scale -> inverse col FFT + transposed store ----
template<int GUARDED, int CONJ, int HALF>
__global__ void __launch_bounds__(TPB, 4)
k_mid(const float2* __restrict__ src, float2* __restrict__ dst){
    __shared__ float sh[ROWS*WREG];
    int tid = threadIdx.x, w = tid >> 5, lane = tid & 31;
    int p = blockIdx.y;
    int row0 = blockIdx.x*ROWS;
    int row = row0 + w;
    size_t poff = (size_t)p * NN;
    const float2* s = src + poff + (size_t)row*N;
    float *Tx = sh + w*WREG, *Ty = Tx + 1088;
    float2 r[32];

    // prefetch this row's Kh (8KB) into L2 so the mid-kernel spectral load hits
    {
        const char* kp = (const char*)(g_KhT + (size_t)row*N);
        asm volatile("prefetch.global.L2 [%0];" :: "l"(kp + lane*256));
        asm volatile("prefetch.global.L2 [%0];" :: "l"(kp + lane*256 + 128));
    }

    #pragma unroll
    for (int j = 0; j < 32; j++)
        r[j] = (!GUARDED || (j >= 8 && j < 24)) ? __ldcs(&s[lane + 32*j]) : make_float2(0.f, 0.f);

    core<0>(r, (float2*)Tx, lane);

    const float2* kh = g_KhT + (size_t)row*N;
    float sc = g_scale;
    #pragma unroll 8
    for (int k = 0; k < 32; k++){
        float2 kv = kh[32*k + lane];
        if (CONJ) kv.y = -kv.y;
        float2 a = r[k];
        r[k] = make_float2((a.x*kv.x - a.y*kv.y)*sc, (a.x*kv.y + a.y*kv.x)*sc);
    }

    core<1>(r, (float2*)Tx, lane);
    stage_out(r, Tx, Ty, lane);
    __syncthreads();

    if (!HALF){
        for (int e = tid; e < ROWS*N; e += TPB){
            int rr = e & 3, i = e >> 2;
            const float* B = sh + rr*WREG;
            __stcs(&dst[poff + (size_t)i*N + (row0 + rr)], make_float2(B[i], B[1088 + i]));
        }
    } else {
        for (int e = tid; e < ROWS*ROI2; e += TPB){
            int rr = e & 3, i = LO + (e >> 2);
            const float* B = sh + rr*WREG;
            __stcs(&dst[poff + (size_t)i*N + (row0 + rr)], make_float2(B[i], B[1088 + i]));
        }
    }
}

// ---- stage 3a: inverse row FFT over APL planes, register-accumulate ----
// Next-plane L2 prefetch overlaps the ~600-cycle DRAM wait with the current core.
__global__ void __launch_bounds__(TPB, 4)
k_last_accum(const float2* __restrict__ src){
    __shared__ float sh[ROWS*WREG];
    int tid = threadIdx.x, w = tid >> 5, lane = tid & 31;
    int row = blockIdx.x*ROWS + w;
    int p0 = blockIdx.y*APL;
    float* Tx = sh + w*WREG;
    float acc[32];
    #pragma unroll
    for (int k = 0; k < 32; k++) acc[k] = 0.f;

    for (int p = p0; p < p0 + APL; p++){
        if (p + 1 < p0 + APL){
            const char* np = (const char*)(src + (size_t)(p+1)*NN + (size_t)row*N);
            asm volatile("prefetch.global.L2 [%0];" :: "l"(np + lane*256));
            asm volatile("prefetch.global.L2 [%0];" :: "l"(np + lane*256 + 128));
        }
        const float2* s = src + (size_t)p*NN + (size_t)row*N;
        float2 r[32];
        #pragma unroll
        for (int j = 0; j < 32; j++) r[j] = __ldcs(&s[lane + 32*j]);
        core<1>(r, (float2*)Tx, lane);
        #pragma unroll
        for (int k = 0; k < 32; k++)
            acc[k] += fmaxf(r[k].x, 0.f) + fmaxf(r[k].y, 0.f);
    }
    float* est = g_ImgEst + (size_t)row*N + lane;
    #pragma unroll
    for (int k = 0; k < 32; k++) atomicAdd(est + 32*k, acc[k]);
}

// ---------------- stage 3b: inverse row FFT + fused obj update ----------------
__global__ void __launch_bounds__(TPB, 4)
k_last_update(const float2* __restrict__ src, float* __restrict__ obj){
    __shared__ float sh[ROWS*WREG];
    int tid = threadIdx.x, w = tid >> 5, lane = tid & 31;
    int row = LO + blockIdx.x*ROWS + w;
    const float2* s = src + (size_t)row*N;
    float* Tx = sh + w*WREG;
    float2 r[32];
    #pragma unroll
    for (int j = 0; j < 32; j++) r[j] = __ldcs(&s[lane + 32*j]);
    core<1>(r, (float2*)Tx, lane);

    float b[16];
    #pragma unroll
    for (int k = 0; k < 16; k++) b[k] = fmaxf(r[k+8].x, 0.f);

    float* o = obj + (size_t)(row - LO)*ROI2 + lane;
    #pragma unroll
    for (int z = 0; z < NZ; z++){
        float* oz = o + (size_t)z*ROI2*ROI2;
        #pragma unroll
        for (int k = 0; k < 16; k++){
            int c = 32*(k+8) - LO;
            oz[c] *= b[k];
        }
    }
}

// ---------------- median (exact, 2-level radix select, 4 launches) ----------------
__global__ void k_hist_top(){
    for (int i = blockIdx.x*blockDim.x + threadIdx.x; i < NN; i += gridDim.x*blockDim.x){
        unsigned u = __float_as_uint(g_ImgEst[i]);
        atomicAdd(&g_hist[u >> 16], 1u);
    }
}

__global__ void k_scan_top(){
    __shared__ unsigned part[1024];
    int t = threadIdx.x;
    unsigned local = 0;
    for (int i = 0; i < 64; i++) local += g_hist[(t<<6) + i];
    part[t] = local; __syncthreads();
    for (int off = 1; off < 1024; off <<= 1){
        unsigned v = (t >= off) ? part[t-off] : 0u;
        __syncthreads();
        part[t] += v;
        __syncthreads();
    }
    unsigned cum = part[t] - local;
    for (int i = 0; i < 64; i++){
        unsigned c = g_hist[(t<<6) + i];
        if (KSEL0 >= cum && KSEL0 < cum + c){ g_sel[0] = (t<<6)+i; g_sel[1] = KSEL0 - cum; }
        if (KSEL1 >= cum && KSEL1 < cum + c){ g_sel[2] = (t<<6)+i; g_sel[3] = KSEL1 - cum; }
        cum += c;
    }
}

__global__ void k_hist_low(){
    unsigned b0 = g_sel[0], b1 = g_sel[2];
    for (int i = blockIdx.x*blockDim.x + threadIdx.x; i < NN; i += gridDim.x*blockDim.x){
        unsigned u = __float_as_uint(g_ImgEst[i]);
        unsigned hi = u >> 16, lo = u & 0xFFFFu;
        if (hi == b0) atomicAdd(&g_hist[65536  + lo], 1u);
        if (hi == b1) atomicAdd(&g_hist[131072 + lo], 1u);
    }
}

__global__ void k_scan_low(){
    __shared__ unsigned part[1024];
    __shared__ unsigned sval[2];
    int t = threadIdx.x;
    #pragma unroll
    for (int which = 0; which < 2; which++){
        const unsigned* H = g_hist + 65536*(which+1);
        unsigned local = 0;
        for (int i = 0; i < 64; i++) local += H[(t<<6) + i];
        part[t] = local; __syncthreads();
        for (int off = 1; off < 1024; off <<= 1){
            unsigned v = (t >= off) ? part[t-off] : 0u;
            __syncthreads();
            part[t] += v;
            __syncthreads();
        }
        unsigned cum = part[t] - local;
        unsigned k   = g_sel[which*2 + 1];
        unsigned bin = g_sel[which*2];
        for (int i = 0; i < 64; i++){
            unsigned c = H[(t<<6) + i];
            if (k >= cum && k < cum + c) sval[which] = (bin << 16) | ((t<<6) + i);
            cum += c;
        }
        __syncthreads();
    }
    if (t == 0){
        float v0 = __uint_as_float(sval[0]);
        float v1 = __uint_as_float(sval[1]);
        g_medScale = 0.5f*(v0 + v1) / SNRV;
    }
}

// ---------------- launch sequence ----------------
extern "C" void kernel_launch(void* const* d_in, const int* in_sizes, int n_in,
                              void* d_out, int out_size)
{
    const float* imstack   = (const float*)d_in[0];
    const float* init_vol  = (const float*)d_in[1];
    const float* conv_real = (const float*)d_in[2];
    const float* conv_imag = (const float*)d_in[3];
    float* obj = (float*)d_out;

    void *wp, *w2p, *histPtr, *estPtr;
    cudaGetSymbolAddress(&wp,  g_W);
    cudaGetSymbolAddress(&w2p, g_W2);
    cudaGetSymbolAddress(&histPtr, g_hist);
    cudaGetSymbolAddress(&estPtr,  g_ImgEst);
    float2* W  = (float2*)wp;
    float2* W2 = (float2*)w2p;

    cudaMemcpyAsync(obj, init_vol, (size_t)NZ*ROI2*ROI2*sizeof(float),
                    cudaMemcpyDeviceToDevice, 0);

    dim3 gHalf12(ROI2/ROWS, PAIRS), g12(N/ROWS, PAIRS);
    dim3 gHalf1 (ROI2/ROWS, 1),     g1 (N/ROWS, 1);
    dim3 gAcc   (N/ROWS, PAIRS/APL);

    // prefix ordering: 5th launch (incl. memcpy) = k_mid -> ncu capture target
    k_ksum<<<256,256>>>((const float4*)conv_real);
    k_kh<<<NN/256,256>>>(conv_real, conv_imag);
    k_fwd1<0><<<gHalf12, TPB>>>(obj, W2);
    k_mid<1,0,0><<<g12, TPB>>>(W2, W);                  // <- ncu target
    k_imgexp<<<NN/256,256>>>(imstack);

    for (int it = 0; it < ITN; it++){
        if (it > 0){
            k_fwd1<0><<<gHalf12, TPB>>>(obj, W2);
            k_mid<1,0,0><<<g12, TPB>>>(W2, W);
        }
        cudaMemsetAsync(estPtr, 0, NN*sizeof(float), 0);
        k_last_accum<<<gAcc, TPB>>>(W);

        // ---- exact median of ImgEst ----
        cudaMemsetAsync(histPtr, 0, 3*65536*sizeof(unsigned), 0);
        k_hist_top<<<512,256>>>();
        k_scan_top<<<1,1024>>>();
        k_hist_low<<<512,256>>>();
        k_scan_low<<<1,1024>>>();

        // ---- back projection: 3 fused stages ----
        k_fwd1<1><<<g1, TPB>>>(nullptr, W2);
        k_mid<0,1,1><<<g1, TPB>>>(W2, W);
        k_last_update<<<gHalf1, TPB>>>(W, obj);
    }
}